// round 1
// baseline (speedup 1.0000x reference)
#include <cuda_runtime.h>
#include <math.h>

// Problem constants
#define NN     20000
#define NE     320000
#define HID    10      // GRU hidden / node feature size
#define NIN    9       // node inputs
#define EF     11      // edge features / message size
#define MSGD   96      // MLP hidden size
#define IN1    31      // 2*HID + EF
#define NITER  7
#define NT     256     // threads per CTA in edge kernel

// Packed (transposed) weight blob layout, in floats
#define W1T_OFF 0
#define W2T_OFF (IN1*MSGD)                 // 2976
#define W3T_OFF (W2T_OFF + MSGD*MSGD)      // 12192
#define W4T_OFF (W3T_OFF + MSGD*MSGD)      // 21408 (padded to 12 outputs)
#define B1_OFF  (W4T_OFF + MSGD*12)        // 22560
#define B2_OFF  (B1_OFF + MSGD)
#define B3_OFF  (B2_OFF + MSGD)
#define B4_OFF  (B3_OFF + MSGD)            // 22848 (12 padded)
#define WPACK   (B4_OFF + 12)              // 22860 floats = 91440 B

#define EDGE_SMEM_FLOATS (WPACK + MSGD*NT) // 22860 + 24576 = 47436
#define EDGE_SMEM_BYTES  (EDGE_SMEM_FLOATS * 4)   // 189744 B

// Scratch (no allocations allowed)
__device__ float g_wpack[WPACK];
__device__ float g_h[2][NN * HID];
__device__ float g_agg[NN * EF];

// ---------------------------------------------------------------------------
// Prep: transpose weights into [k][j] layout + pack biases (once per launch)
// ---------------------------------------------------------------------------
__global__ void prep_kernel(const float* __restrict__ W1, const float* __restrict__ b1,
                            const float* __restrict__ W2, const float* __restrict__ b2,
                            const float* __restrict__ W3, const float* __restrict__ b3,
                            const float* __restrict__ W4, const float* __restrict__ b4)
{
    int i = blockIdx.x * blockDim.x + threadIdx.x;
    if (i >= WPACK) return;
    float v;
    if (i < W2T_OFF) {
        int r = i - W1T_OFF; int k = r / MSGD, j = r % MSGD;
        v = W1[j * IN1 + k];
    } else if (i < W3T_OFF) {
        int r = i - W2T_OFF; int k = r / MSGD, j = r % MSGD;
        v = W2[j * MSGD + k];
    } else if (i < W4T_OFF) {
        int r = i - W3T_OFF; int k = r / MSGD, j = r % MSGD;
        v = W3[j * MSGD + k];
    } else if (i < B1_OFF) {
        int r = i - W4T_OFF; int k = r / 12, j = r % 12;
        v = (j < EF) ? W4[j * MSGD + k] : 0.0f;
    } else if (i < B2_OFF) {
        v = b1[i - B1_OFF];
    } else if (i < B3_OFF) {
        v = b2[i - B2_OFF];
    } else if (i < B4_OFF) {
        v = b3[i - B3_OFF];
    } else {
        int j = i - B4_OFF;
        v = (j < EF) ? b4[j] : 0.0f;
    }
    g_wpack[i] = v;
}

__global__ void zero_h0_kernel()
{
    int i = blockIdx.x * blockDim.x + threadIdx.x;
    if (i < NN * HID) g_h[0][i] = 0.0f;
}

__global__ void zero_agg_kernel()
{
    int i = blockIdx.x * blockDim.x + threadIdx.x;
    if (i < NN * EF) g_agg[i] = 0.0f;
}

// ---------------------------------------------------------------------------
// Fused edge MLP + scatter-add
// Thread-per-edge. Activation vector in a thread-private SMEM column
// (stride NT -> conflict-free). Accumulators in registers (j fully unrolled,
// k rolled). Weights broadcast from SMEM via float4 loads.
// ---------------------------------------------------------------------------
__device__ __forceinline__ void mlp_layer96(const float* __restrict__ sm,
                                            float* __restrict__ col,
                                            int w_off, int b_off)
{
    float acc[MSGD];
#pragma unroll
    for (int j = 0; j < MSGD; j++) acc[j] = sm[b_off + j];
#pragma unroll 2
    for (int k = 0; k < MSGD; k++) {
        float x = col[k * NT];
        const float4* w = (const float4*)(sm + w_off + k * MSGD);
#pragma unroll
        for (int j4 = 0; j4 < MSGD / 4; j4++) {
            float4 wv = w[j4];
            acc[4 * j4 + 0] = fmaf(wv.x, x, acc[4 * j4 + 0]);
            acc[4 * j4 + 1] = fmaf(wv.y, x, acc[4 * j4 + 1]);
            acc[4 * j4 + 2] = fmaf(wv.z, x, acc[4 * j4 + 2]);
            acc[4 * j4 + 3] = fmaf(wv.w, x, acc[4 * j4 + 3]);
        }
    }
#pragma unroll
    for (int j = 0; j < MSGD; j++) col[j * NT] = fmaxf(acc[j], 0.0f);
}

__global__ __launch_bounds__(NT, 1)
void edge_kernel(int parity,
                 const float* __restrict__ edge_attr,
                 const int* __restrict__ src,
                 const int* __restrict__ dst)
{
    extern __shared__ float sm[];
    // Stage packed weights+biases into SMEM
    for (int i = threadIdx.x; i < WPACK; i += NT) sm[i] = g_wpack[i];
    __syncthreads();

    float* sAct = sm + WPACK;
    const float* __restrict__ h = g_h[parity];

    int e = blockIdx.x * NT + threadIdx.x;
    if (e >= NE) return;
    int s = src[e];
    int d = dst[e];

    float* col = sAct + threadIdx.x;   // stride-NT column, thread-private

    // Gather inputs: [h[src](10) | h[dst](10) | edge_attr(11)]
#pragma unroll
    for (int i = 0; i < HID; i++) col[i * NT] = __ldg(&h[s * HID + i]);
#pragma unroll
    for (int i = 0; i < HID; i++) col[(HID + i) * NT] = __ldg(&h[d * HID + i]);
#pragma unroll
    for (int i = 0; i < EF; i++) col[(2 * HID + i) * NT] = edge_attr[e * EF + i];

    // Layer 1: 31 -> 96, relu
    {
        float acc[MSGD];
#pragma unroll
        for (int j = 0; j < MSGD; j++) acc[j] = sm[B1_OFF + j];
#pragma unroll 2
        for (int k = 0; k < IN1; k++) {
            float x = col[k * NT];
            const float4* w = (const float4*)(sm + W1T_OFF + k * MSGD);
#pragma unroll
            for (int j4 = 0; j4 < MSGD / 4; j4++) {
                float4 wv = w[j4];
                acc[4 * j4 + 0] = fmaf(wv.x, x, acc[4 * j4 + 0]);
                acc[4 * j4 + 1] = fmaf(wv.y, x, acc[4 * j4 + 1]);
                acc[4 * j4 + 2] = fmaf(wv.z, x, acc[4 * j4 + 2]);
                acc[4 * j4 + 3] = fmaf(wv.w, x, acc[4 * j4 + 3]);
            }
        }
#pragma unroll
        for (int j = 0; j < MSGD; j++) col[j * NT] = fmaxf(acc[j], 0.0f);
    }

    // Layers 2, 3: 96 -> 96, relu
    mlp_layer96(sm, col, W2T_OFF, B2_OFF);
    mlp_layer96(sm, col, W3T_OFF, B3_OFF);

    // Layer 4: 96 -> 11 (padded to 12), no relu, then scatter-add
    {
        float a4[12];
#pragma unroll
        for (int j = 0; j < 12; j++) a4[j] = sm[B4_OFF + j];
#pragma unroll 2
        for (int k = 0; k < MSGD; k++) {
            float x = col[k * NT];
            const float4* w = (const float4*)(sm + W4T_OFF + k * 12);
#pragma unroll
            for (int j4 = 0; j4 < 3; j4++) {
                float4 wv = w[j4];
                a4[4 * j4 + 0] = fmaf(wv.x, x, a4[4 * j4 + 0]);
                a4[4 * j4 + 1] = fmaf(wv.y, x, a4[4 * j4 + 1]);
                a4[4 * j4 + 2] = fmaf(wv.z, x, a4[4 * j4 + 2]);
                a4[4 * j4 + 3] = fmaf(wv.w, x, a4[4 * j4 + 3]);
            }
        }
#pragma unroll
        for (int j = 0; j < EF; j++) atomicAdd(&g_agg[d * EF + j], a4[j]);
    }
}

// ---------------------------------------------------------------------------
// GRU cell + output head, thread-per-node
// ---------------------------------------------------------------------------
__global__ void gru_kernel(int parity,
                           const float* __restrict__ node_in,
                           const float* __restrict__ wih,  // [30][20]
                           const float* __restrict__ whh,  // [30][10]
                           const float* __restrict__ bih,  // [30]
                           const float* __restrict__ bhh,  // [30]
                           const float* __restrict__ fw,   // [2][10]
                           const float* __restrict__ fb,   // [2]
                           float* __restrict__ out)        // [NN][2] slice
{
    __shared__ float s[600 + 300 + 30 + 30 + 20 + 2];
    int tid = threadIdx.x;
    for (int i = tid; i < 600; i += blockDim.x) s[i] = wih[i];
    for (int i = tid; i < 300; i += blockDim.x) s[600 + i] = whh[i];
    for (int i = tid; i < 30; i += blockDim.x) { s[900 + i] = bih[i]; s[930 + i] = bhh[i]; }
    for (int i = tid; i < 20; i += blockDim.x) s[960 + i] = fw[i];
    for (int i = tid; i < 2; i += blockDim.x) s[980 + i] = fb[i];
    __syncthreads();

    int n = blockIdx.x * blockDim.x + tid;
    if (n >= NN) return;

    const float* __restrict__ h = g_h[parity] + n * HID;
    float* __restrict__ hn = g_h[1 - parity] + n * HID;

    float x[20], hv[HID];
#pragma unroll
    for (int i = 0; i < EF; i++) x[i] = g_agg[n * EF + i];
#pragma unroll
    for (int i = 0; i < NIN; i++) x[EF + i] = node_in[n * NIN + i];
#pragma unroll
    for (int i = 0; i < HID; i++) hv[i] = h[i];

    float gi[30], gh[30];
#pragma unroll
    for (int g = 0; g < 30; g++) {
        float a = s[900 + g];
#pragma unroll
        for (int k = 0; k < 20; k++) a = fmaf(s[g * 20 + k], x[k], a);
        gi[g] = a;
        float b = s[930 + g];
#pragma unroll
        for (int k = 0; k < 10; k++) b = fmaf(s[600 + g * 10 + k], hv[k], b);
        gh[g] = b;
    }

    float hnew[HID];
#pragma unroll
    for (int i = 0; i < HID; i++) {
        float r = 1.0f / (1.0f + expf(-(gi[i] + gh[i])));
        float z = 1.0f / (1.0f + expf(-(gi[10 + i] + gh[10 + i])));
        float nval = tanhf(gi[20 + i] + r * gh[20 + i]);
        float hni = (1.0f - z) * nval + z * hv[i];
        hnew[i] = hni;
        hn[i] = hni;
    }

#pragma unroll
    for (int o = 0; o < 2; o++) {
        float a = s[980 + o];
#pragma unroll
        for (int k = 0; k < HID; k++) a = fmaf(s[960 + o * 10 + k], hnew[k], a);
        out[n * 2 + o] = a;
    }
}

// ---------------------------------------------------------------------------
// Launch
// ---------------------------------------------------------------------------
extern "C" void kernel_launch(void* const* d_in, const int* in_sizes, int n_in,
                              void* d_out, int out_size)
{
    const float* node_in   = (const float*)d_in[0];
    const float* edge_attr = (const float*)d_in[1];
    const float* W1 = (const float*)d_in[2];  const float* b1 = (const float*)d_in[3];
    const float* W2 = (const float*)d_in[4];  const float* b2 = (const float*)d_in[5];
    const float* W3 = (const float*)d_in[6];  const float* b3 = (const float*)d_in[7];
    const float* W4 = (const float*)d_in[8];  const float* b4 = (const float*)d_in[9];
    const float* wih = (const float*)d_in[10]; const float* whh = (const float*)d_in[11];
    const float* bih = (const float*)d_in[12]; const float* bhh = (const float*)d_in[13];
    const float* fw  = (const float*)d_in[14]; const float* fb  = (const float*)d_in[15];
    const int* src = (const int*)d_in[16];
    const int* dst = (const int*)d_in[17];
    float* out = (float*)d_out;

    cudaFuncSetAttribute(edge_kernel,
                         cudaFuncAttributeMaxDynamicSharedMemorySize,
                         EDGE_SMEM_BYTES);

    prep_kernel<<<(WPACK + 255) / 256, 256>>>(W1, b1, W2, b2, W3, b3, W4, b4);
    zero_h0_kernel<<<(NN * HID + 255) / 256, 256>>>();

    for (int t = 0; t < NITER; t++) {
        int p = t & 1;
        zero_agg_kernel<<<(NN * EF + 255) / 256, 256>>>();
        edge_kernel<<<NE / NT, NT, EDGE_SMEM_BYTES>>>(p, edge_attr, src, dst);
        gru_kernel<<<(NN + 127) / 128, 128>>>(p, node_in, wih, whh, bih, bhh,
                                              fw, fb, out + (size_t)t * NN * 2);
    }
}

// round 3
// speedup vs baseline: 1.1591x; 1.1591x over previous
#include <cuda_runtime.h>
#include <math.h>

// Problem constants
#define NN     20000
#define NE     320000
#define HID    10      // GRU hidden / node feature size
#define NIN    9       // node inputs
#define EF     11      // edge features / message size
#define MSGD   96      // MLP hidden size
#define IN1    31      // 2*HID + EF
#define NITER  7

#define ES     128     // edges per CTA tile
#define NTHR   192     // 16 x 12 thread grid

// Packed (transposed) weight blob layout, in floats
#define W1T_OFF 0
#define W2T_OFF (IN1*MSGD)                 // 2976
#define W3T_OFF (W2T_OFF + MSGD*MSGD)      // 12192
#define W4T_OFF (W3T_OFF + MSGD*MSGD)      // 21408 (padded to 12 outputs)
#define B1_OFF  (W4T_OFF + MSGD*12)        // 22560
#define B2_OFF  (B1_OFF + MSGD)
#define B3_OFF  (B2_OFF + MSGD)
#define B4_OFF  (B3_OFF + MSGD)            // (12 padded)
#define WPACK   (B4_OFF + 12)              // 22860 floats = 91440 B

// Edge-kernel dynamic smem: weights + two act tiles + ids
#define EDGE_SMEM_FLOATS (WPACK + 2*MSGD*ES + 2*ES)   // 22860+24576+256 = 47692
#define EDGE_SMEM_BYTES  (EDGE_SMEM_FLOATS * 4)       // 190768 B

// Scratch (no allocations allowed)
__device__ __align__(16) float g_wpack[WPACK];
__device__ float g_h[2][NN * HID];
__device__ float g_agg[NN * EF];

// ---------------------------------------------------------------------------
// Packed fp32x2 FMA (Blackwell): one issue slot, two fp32 FMAs
// ---------------------------------------------------------------------------
__device__ __forceinline__ float2 ffma2(float2 a, float2 b, float2 c)
{
    unsigned long long ua = *reinterpret_cast<unsigned long long*>(&a);
    unsigned long long ub = *reinterpret_cast<unsigned long long*>(&b);
    unsigned long long uc = *reinterpret_cast<unsigned long long*>(&c);
    unsigned long long ud;
    asm("fma.rn.f32x2 %0, %1, %2, %3;" : "=l"(ud) : "l"(ua), "l"(ub), "l"(uc));
    return *reinterpret_cast<float2*>(&ud);
}

// ---------------------------------------------------------------------------
// Prep: transpose weights into [k][j] layout + pack biases (once per launch)
// ---------------------------------------------------------------------------
__global__ void prep_kernel(const float* __restrict__ W1, const float* __restrict__ b1,
                            const float* __restrict__ W2, const float* __restrict__ b2,
                            const float* __restrict__ W3, const float* __restrict__ b3,
                            const float* __restrict__ W4, const float* __restrict__ b4)
{
    int i = blockIdx.x * blockDim.x + threadIdx.x;
    if (i >= WPACK) return;
    float v;
    if (i < W2T_OFF) {
        int r = i - W1T_OFF; int k = r / MSGD, j = r % MSGD;
        v = W1[j * IN1 + k];
    } else if (i < W3T_OFF) {
        int r = i - W2T_OFF; int k = r / MSGD, j = r % MSGD;
        v = W2[j * MSGD + k];
    } else if (i < W4T_OFF) {
        int r = i - W3T_OFF; int k = r / MSGD, j = r % MSGD;
        v = W3[j * MSGD + k];
    } else if (i < B1_OFF) {
        int r = i - W4T_OFF; int k = r / 12, j = r % 12;
        v = (j < EF) ? W4[j * MSGD + k] : 0.0f;
    } else if (i < B2_OFF) {
        v = b1[i - B1_OFF];
    } else if (i < B3_OFF) {
        v = b2[i - B2_OFF];
    } else if (i < B4_OFF) {
        v = b3[i - B3_OFF];
    } else {
        int j = i - B4_OFF;
        v = (j < EF) ? b4[j] : 0.0f;
    }
    g_wpack[i] = v;
}

__global__ void zero_h0_kernel()
{
    int i = blockIdx.x * blockDim.x + threadIdx.x;
    if (i < NN * HID) g_h[0][i] = 0.0f;
}

__global__ void zero_agg_kernel()
{
    int i = blockIdx.x * blockDim.x + threadIdx.x;
    if (i < NN * EF) g_agg[i] = 0.0f;
}

// ---------------------------------------------------------------------------
// One GEMM layer on a [K x 128] activation tile -> [96 x 128] output tile.
// Thread (tx,ty) computes outputs j0..j0+7 for 8 edge-columns:
//   columns {tx*4 .. tx*4+3} and {64+tx*4 .. 64+tx*4+3}  (conflict-free frags)
// Weights/bias broadcast from smem. ReLU applied on store.
// ---------------------------------------------------------------------------
template<int K>
__device__ __forceinline__ void gemm_tile(const float* __restrict__ sw,
                                          int w_off, int b_off,
                                          const float* __restrict__ sin,
                                          float* __restrict__ sout,
                                          int tx, int ty)
{
    const int j0 = ty * 8;
    const int c0 = tx * 4;
    float2 acc[8][4];
#pragma unroll
    for (int j = 0; j < 8; j++) {
        float b = sw[b_off + j0 + j];
        float2 bb = make_float2(b, b);
#pragma unroll
        for (int p = 0; p < 4; p++) acc[j][p] = bb;
    }

#pragma unroll 2
    for (int k = 0; k < K; k++) {
        const float* xr = sin + k * ES;
        float4 xa = *(const float4*)(xr + c0);
        float4 xb = *(const float4*)(xr + 64 + c0);
        float2 xp[4];
        xp[0] = make_float2(xa.x, xa.y);  xp[1] = make_float2(xa.z, xa.w);
        xp[2] = make_float2(xb.x, xb.y);  xp[3] = make_float2(xb.z, xb.w);

        const float* wr = sw + w_off + k * MSGD + j0;
        float4 wA = *(const float4*)(wr);
        float4 wB = *(const float4*)(wr + 4);
        float wj[8] = { wA.x, wA.y, wA.z, wA.w, wB.x, wB.y, wB.z, wB.w };

#pragma unroll
        for (int j = 0; j < 8; j++) {
            float2 ww = make_float2(wj[j], wj[j]);
#pragma unroll
            for (int p = 0; p < 4; p++)
                acc[j][p] = ffma2(ww, xp[p], acc[j][p]);
        }
    }

#pragma unroll
    for (int j = 0; j < 8; j++) {
        float* orow = sout + (j0 + j) * ES;
        float4 o1 = make_float4(fmaxf(acc[j][0].x, 0.0f), fmaxf(acc[j][0].y, 0.0f),
                                fmaxf(acc[j][1].x, 0.0f), fmaxf(acc[j][1].y, 0.0f));
        float4 o2 = make_float4(fmaxf(acc[j][2].x, 0.0f), fmaxf(acc[j][2].y, 0.0f),
                                fmaxf(acc[j][3].x, 0.0f), fmaxf(acc[j][3].y, 0.0f));
        *(float4*)(orow + c0) = o1;
        *(float4*)(orow + 64 + c0) = o2;
    }
}

// ---------------------------------------------------------------------------
// Fused edge MLP (tiled SGEMM) + scatter-add
// ---------------------------------------------------------------------------
__global__ __launch_bounds__(NTHR, 1)
void edge_kernel(int parity,
                 const float* __restrict__ edge_attr,
                 const int* __restrict__ src,
                 const int* __restrict__ dst)
{
    extern __shared__ float sm[];
    float* sw   = sm;
    float* bufA = sm + WPACK;
    float* bufB = bufA + MSGD * ES;
    int*   ids  = (int*)(bufB + MSGD * ES);   // src[128] | dst[128]

    const int tid = threadIdx.x;
    const int ebase = blockIdx.x * ES;

    // Stage weights (float4 copies) + edge ids
    for (int i = tid; i < WPACK / 4; i += NTHR)
        ((float4*)sw)[i] = ((const float4*)g_wpack)[i];
    if (tid < ES) {
        ids[tid]      = src[ebase + tid];
        ids[ES + tid] = dst[ebase + tid];
    }
    __syncthreads();

    const float* __restrict__ h = g_h[parity];

    // Gather input tile into bufB: rows 0..9 = h[src], 10..19 = h[dst], 20..30 = edge_attr
    for (int i = tid; i < ES * 2 * HID; i += NTHR) {
        int r = i / ES, c = i - r * ES;
        int node = (r < HID) ? ids[c] : ids[ES + c];
        int rr   = (r < HID) ? r : r - HID;
        bufB[r * ES + c] = h[node * HID + rr];
    }
    for (int i = tid; i < ES * EF; i += NTHR) {
        int e = i / EF, f = i - e * EF;   // coalesced gmem read order
        bufB[(2 * HID + f) * ES + e] = edge_attr[(size_t)(ebase + e) * EF + f];
    }
    __syncthreads();

    const int tx = tid & 15;
    const int ty = tid >> 4;    // 0..11

    gemm_tile<IN1 >(sw, W1T_OFF, B1_OFF, bufB, bufA, tx, ty);
    __syncthreads();
    gemm_tile<MSGD>(sw, W2T_OFF, B2_OFF, bufA, bufB, tx, ty);
    __syncthreads();
    gemm_tile<MSGD>(sw, W3T_OFF, B3_OFF, bufB, bufA, tx, ty);
    __syncthreads();

    // Layer 4: 96 -> 12 (11 real). Thread handles out j = ty, 8 edge-columns.
    {
        const int c0 = tx * 4;
        float bias = sw[B4_OFF + ty];
        float2 acc[4];
#pragma unroll
        for (int p = 0; p < 4; p++) acc[p] = make_float2(bias, bias);

#pragma unroll 2
        for (int k = 0; k < MSGD; k++) {
            float w = sw[W4T_OFF + k * 12 + ty];
            float2 ww = make_float2(w, w);
            const float* xr = bufA + k * ES;
            float4 xa = *(const float4*)(xr + c0);
            float4 xb = *(const float4*)(xr + 64 + c0);
            acc[0] = ffma2(ww, make_float2(xa.x, xa.y), acc[0]);
            acc[1] = ffma2(ww, make_float2(xa.z, xa.w), acc[1]);
            acc[2] = ffma2(ww, make_float2(xb.x, xb.y), acc[2]);
            acc[3] = ffma2(ww, make_float2(xb.z, xb.w), acc[3]);
        }

        if (ty < EF) {
            const int* dsts = ids + ES;
#pragma unroll
            for (int p = 0; p < 4; p++) {
                int c = (p < 2) ? (c0 + 2 * p) : (64 + c0 + 2 * (p - 2));
                atomicAdd(&g_agg[dsts[c]     * EF + ty], acc[p].x);
                atomicAdd(&g_agg[dsts[c + 1] * EF + ty], acc[p].y);
            }
        }
    }
}

// ---------------------------------------------------------------------------
// GRU cell + output head, thread-per-node
// ---------------------------------------------------------------------------
__global__ void gru_kernel(int parity,
                           const float* __restrict__ node_in,
                           const float* __restrict__ wih,  // [30][20]
                           const float* __restrict__ whh,  // [30][10]
                           const float* __restrict__ bih,  // [30]
                           const float* __restrict__ bhh,  // [30]
                           const float* __restrict__ fw,   // [2][10]
                           const float* __restrict__ fb,   // [2]
                           float* __restrict__ out)        // [NN][2] slice
{
    __shared__ float s[600 + 300 + 30 + 30 + 20 + 2];
    int tid = threadIdx.x;
    for (int i = tid; i < 600; i += blockDim.x) s[i] = wih[i];
    for (int i = tid; i < 300; i += blockDim.x) s[600 + i] = whh[i];
    for (int i = tid; i < 30; i += blockDim.x) { s[900 + i] = bih[i]; s[930 + i] = bhh[i]; }
    for (int i = tid; i < 20; i += blockDim.x) s[960 + i] = fw[i];
    for (int i = tid; i < 2; i += blockDim.x) s[980 + i] = fb[i];
    __syncthreads();

    int n = blockIdx.x * blockDim.x + tid;
    if (n >= NN) return;

    const float* __restrict__ hp = g_h[parity] + n * HID;
    float* __restrict__ hn = g_h[1 - parity] + n * HID;

    float x[20], hv[HID];
#pragma unroll
    for (int i = 0; i < EF; i++) x[i] = g_agg[n * EF + i];
#pragma unroll
    for (int i = 0; i < NIN; i++) x[EF + i] = node_in[n * NIN + i];
#pragma unroll
    for (int i = 0; i < HID; i++) hv[i] = hp[i];

    float gi[30], gh[30];
#pragma unroll
    for (int g = 0; g < 30; g++) {
        float a = s[900 + g];
#pragma unroll
        for (int k = 0; k < 20; k++) a = fmaf(s[g * 20 + k], x[k], a);
        gi[g] = a;
        float b = s[930 + g];
#pragma unroll
        for (int k = 0; k < 10; k++) b = fmaf(s[600 + g * 10 + k], hv[k], b);
        gh[g] = b;
    }

    float hnew[HID];
#pragma unroll
    for (int i = 0; i < HID; i++) {
        float r = 1.0f / (1.0f + expf(-(gi[i] + gh[i])));
        float z = 1.0f / (1.0f + expf(-(gi[10 + i] + gh[10 + i])));
        float nval = tanhf(gi[20 + i] + r * gh[20 + i]);
        float hni = (1.0f - z) * nval + z * hv[i];
        hnew[i] = hni;
        hn[i] = hni;
    }

#pragma unroll
    for (int o = 0; o < 2; o++) {
        float a = s[980 + o];
#pragma unroll
        for (int k = 0; k < HID; k++) a = fmaf(s[960 + o * 10 + k], hnew[k], a);
        out[n * 2 + o] = a;
    }
}

// ---------------------------------------------------------------------------
// Launch
// ---------------------------------------------------------------------------
extern "C" void kernel_launch(void* const* d_in, const int* in_sizes, int n_in,
                              void* d_out, int out_size)
{
    const float* node_in   = (const float*)d_in[0];
    const float* edge_attr = (const float*)d_in[1];
    const float* W1 = (const float*)d_in[2];  const float* b1 = (const float*)d_in[3];
    const float* W2 = (const float*)d_in[4];  const float* b2 = (const float*)d_in[5];
    const float* W3 = (const float*)d_in[6];  const float* b3 = (const float*)d_in[7];
    const float* W4 = (const float*)d_in[8];  const float* b4 = (const float*)d_in[9];
    const float* wih = (const float*)d_in[10]; const float* whh = (const float*)d_in[11];
    const float* bih = (const float*)d_in[12]; const float* bhh = (const float*)d_in[13];
    const float* fw  = (const float*)d_in[14]; const float* fb  = (const float*)d_in[15];
    const int* src = (const int*)d_in[16];
    const int* dst = (const int*)d_in[17];
    float* out = (float*)d_out;

    cudaFuncSetAttribute(edge_kernel,
                         cudaFuncAttributeMaxDynamicSharedMemorySize,
                         EDGE_SMEM_BYTES);

    prep_kernel<<<(WPACK + 255) / 256, 256>>>(W1, b1, W2, b2, W3, b3, W4, b4);
    zero_h0_kernel<<<(NN * HID + 255) / 256, 256>>>();

    for (int t = 0; t < NITER; t++) {
        int p = t & 1;
        zero_agg_kernel<<<(NN * EF + 255) / 256, 256>>>();
        edge_kernel<<<NE / ES, NTHR, EDGE_SMEM_BYTES>>>(p, edge_attr, src, dst);
        gru_kernel<<<(NN + 127) / 128, 128>>>(p, node_in, wih, whh, bih, bhh,
                                              fw, fb, out + (size_t)t * NN * 2);
    }
}

// round 4
// speedup vs baseline: 1.3716x; 1.1833x over previous
#include <cuda_runtime.h>
#include <math.h>

// Problem constants
#define NN     20000
#define NE     320000
#define HID    10      // GRU hidden / node feature size
#define NIN    9       // node inputs
#define EF     11      // edge features / message size
#define MSGD   96      // MLP hidden size
#define IN1    31      // 2*HID + EF
#define NITER  7

#define ES     128     // edges per CTA tile
#define NTHR   384     // 16 x 24 thread grid

// Packed (transposed) weight blob layout, in floats
#define W1T_OFF 0
#define W2T_OFF (IN1*MSGD)                 // 2976
#define W3T_OFF (W2T_OFF + MSGD*MSGD)      // 12192
#define W4T_OFF (W3T_OFF + MSGD*MSGD)      // 21408 (padded to 12 outputs)
#define B1_OFF  (W4T_OFF + MSGD*12)        // 22560
#define B2_OFF  (B1_OFF + MSGD)
#define B3_OFF  (B2_OFF + MSGD)
#define B4_OFF  (B3_OFF + MSGD)            // (12 padded)
#define WPACK   (B4_OFF + 12)              // 22860 floats = 91440 B

// Edge-kernel dynamic smem: weights + two act tiles + ids
#define EDGE_SMEM_FLOATS (WPACK + 2*MSGD*ES + 2*ES)   // 47692
#define EDGE_SMEM_BYTES  (EDGE_SMEM_FLOATS * 4)       // 190768 B

// Scratch (no allocations allowed)
__device__ __align__(16) float g_wpack[WPACK];
__device__ float g_h[2][NN * HID];
__device__ float g_agg[NN * EF];

// ---------------------------------------------------------------------------
// Packed fp32x2 FMA (Blackwell): one issue slot, two fp32 FMAs
// ---------------------------------------------------------------------------
__device__ __forceinline__ float2 ffma2(float2 a, float2 b, float2 c)
{
    unsigned long long ua = *reinterpret_cast<unsigned long long*>(&a);
    unsigned long long ub = *reinterpret_cast<unsigned long long*>(&b);
    unsigned long long uc = *reinterpret_cast<unsigned long long*>(&c);
    unsigned long long ud;
    asm("fma.rn.f32x2 %0, %1, %2, %3;" : "=l"(ud) : "l"(ua), "l"(ub), "l"(uc));
    return *reinterpret_cast<float2*>(&ud);
}

// ---------------------------------------------------------------------------
// Prep: transpose weights into [k][j] layout + pack biases
// ---------------------------------------------------------------------------
__global__ void prep_kernel(const float* __restrict__ W1, const float* __restrict__ b1,
                            const float* __restrict__ W2, const float* __restrict__ b2,
                            const float* __restrict__ W3, const float* __restrict__ b3,
                            const float* __restrict__ W4, const float* __restrict__ b4)
{
    int i = blockIdx.x * blockDim.x + threadIdx.x;
    if (i >= WPACK) return;
    float v;
    if (i < W2T_OFF) {
        int r = i - W1T_OFF; int k = r / MSGD, j = r % MSGD;
        v = W1[j * IN1 + k];
    } else if (i < W3T_OFF) {
        int r = i - W2T_OFF; int k = r / MSGD, j = r % MSGD;
        v = W2[j * MSGD + k];
    } else if (i < W4T_OFF) {
        int r = i - W3T_OFF; int k = r / MSGD, j = r % MSGD;
        v = W3[j * MSGD + k];
    } else if (i < B1_OFF) {
        int r = i - W4T_OFF; int k = r / 12, j = r % 12;
        v = (j < EF) ? W4[j * MSGD + k] : 0.0f;
    } else if (i < B2_OFF) {
        v = b1[i - B1_OFF];
    } else if (i < B3_OFF) {
        v = b2[i - B2_OFF];
    } else if (i < B4_OFF) {
        v = b3[i - B3_OFF];
    } else {
        int j = i - B4_OFF;
        v = (j < EF) ? b4[j] : 0.0f;
    }
    g_wpack[i] = v;
}

__global__ void init_state_kernel()
{
    int i = blockIdx.x * blockDim.x + threadIdx.x;
    if (i < NN * HID) g_h[0][i] = 0.0f;
    if (i < NN * EF) g_agg[i] = 0.0f;
}

// ---------------------------------------------------------------------------
// GEMM layer [K x 128] -> [96 x 128], thread = 4 outputs x 8 edge-columns.
// Software-pipelined: fragments for k+1 prefetched before k's FMAs.
// ---------------------------------------------------------------------------
template<int K>
__device__ __forceinline__ void gemm_tile4(const float* __restrict__ sw,
                                           int w_off, int b_off,
                                           const float* __restrict__ sin,
                                           float* __restrict__ sout,
                                           int tx, int ty)
{
    const int j0 = ty * 4;
    const int c0 = tx * 4;
    float2 acc[4][4];
#pragma unroll
    for (int j = 0; j < 4; j++) {
        float b = sw[b_off + j0 + j];
        float2 bb = make_float2(b, b);
#pragma unroll
        for (int p = 0; p < 4; p++) acc[j][p] = bb;
    }

    // prefetch k = 0
    float4 xa = *(const float4*)(sin + c0);
    float4 xb = *(const float4*)(sin + 64 + c0);
    float4 wv = *(const float4*)(sw + w_off + j0);

#pragma unroll 4
    for (int k = 0; k < K - 1; k++) {
        float4 xa_n = *(const float4*)(sin + (k + 1) * ES + c0);
        float4 xb_n = *(const float4*)(sin + (k + 1) * ES + 64 + c0);
        float4 wv_n = *(const float4*)(sw + w_off + (k + 1) * MSGD + j0);

        float2 xp[4] = { make_float2(xa.x, xa.y), make_float2(xa.z, xa.w),
                         make_float2(xb.x, xb.y), make_float2(xb.z, xb.w) };
        float wj[4] = { wv.x, wv.y, wv.z, wv.w };
#pragma unroll
        for (int j = 0; j < 4; j++) {
            float2 ww = make_float2(wj[j], wj[j]);
#pragma unroll
            for (int p = 0; p < 4; p++)
                acc[j][p] = ffma2(ww, xp[p], acc[j][p]);
        }
        xa = xa_n; xb = xb_n; wv = wv_n;
    }
    {   // last k
        float2 xp[4] = { make_float2(xa.x, xa.y), make_float2(xa.z, xa.w),
                         make_float2(xb.x, xb.y), make_float2(xb.z, xb.w) };
        float wj[4] = { wv.x, wv.y, wv.z, wv.w };
#pragma unroll
        for (int j = 0; j < 4; j++) {
            float2 ww = make_float2(wj[j], wj[j]);
#pragma unroll
            for (int p = 0; p < 4; p++)
                acc[j][p] = ffma2(ww, xp[p], acc[j][p]);
        }
    }

#pragma unroll
    for (int j = 0; j < 4; j++) {
        float* orow = sout + (j0 + j) * ES;
        float4 o1 = make_float4(fmaxf(acc[j][0].x, 0.0f), fmaxf(acc[j][0].y, 0.0f),
                                fmaxf(acc[j][1].x, 0.0f), fmaxf(acc[j][1].y, 0.0f));
        float4 o2 = make_float4(fmaxf(acc[j][2].x, 0.0f), fmaxf(acc[j][2].y, 0.0f),
                                fmaxf(acc[j][3].x, 0.0f), fmaxf(acc[j][3].y, 0.0f));
        *(float4*)(orow + c0) = o1;
        *(float4*)(orow + 64 + c0) = o2;
    }
}

// ---------------------------------------------------------------------------
// Fused edge MLP (tiled SGEMM) + scatter-add
// ---------------------------------------------------------------------------
__global__ __launch_bounds__(NTHR, 1)
void edge_kernel(int parity,
                 const float* __restrict__ edge_attr,
                 const int* __restrict__ src,
                 const int* __restrict__ dst)
{
    extern __shared__ float sm[];
    float* sw   = sm;
    float* bufA = sm + WPACK;
    float* bufB = bufA + MSGD * ES;
    int*   ids  = (int*)(bufB + MSGD * ES);   // src[128] | dst[128]

    const int tid = threadIdx.x;
    const int ebase = blockIdx.x * ES;

    // Stage weights (float4 copies) + edge ids
    for (int i = tid; i < WPACK / 4; i += NTHR)
        ((float4*)sw)[i] = ((const float4*)g_wpack)[i];
    if (tid < ES) {
        ids[tid]      = src[ebase + tid];
        ids[ES + tid] = dst[ebase + tid];
    }
    __syncthreads();

    const float* __restrict__ h = g_h[parity];

    // Gather input tile: rows 0..9 h[src], 10..19 h[dst], 20..30 edge_attr
    for (int i = tid; i < ES * 2 * HID; i += NTHR) {
        int r = i / ES, c = i - r * ES;
        int node = (r < HID) ? ids[c] : ids[ES + c];
        int rr   = (r < HID) ? r : r - HID;
        bufB[r * ES + c] = h[node * HID + rr];
    }
    for (int i = tid; i < ES * EF; i += NTHR) {
        int e = i / EF, f = i - e * EF;
        bufB[(2 * HID + f) * ES + e] = edge_attr[(size_t)(ebase + e) * EF + f];
    }
    __syncthreads();

    const int tx = tid & 15;
    const int ty = tid >> 4;    // 0..23

    gemm_tile4<IN1 >(sw, W1T_OFF, B1_OFF, bufB, bufA, tx, ty);
    __syncthreads();
    gemm_tile4<MSGD>(sw, W2T_OFF, B2_OFF, bufA, bufB, tx, ty);
    __syncthreads();
    gemm_tile4<MSGD>(sw, W3T_OFF, B3_OFF, bufB, bufA, tx, ty);
    __syncthreads();

    // Layer 4: 96 -> 12 (11 real). Threads ty<12: out j = ty, 8 edge-columns.
    if (ty < EF) {
        const int c0 = tx * 4;
        float bias = sw[B4_OFF + ty];
        float2 acc[4];
#pragma unroll
        for (int p = 0; p < 4; p++) acc[p] = make_float2(bias, bias);

        float w0 = sw[W4T_OFF + ty];
        float4 xa = *(const float4*)(bufA + c0);
        float4 xb = *(const float4*)(bufA + 64 + c0);

#pragma unroll 4
        for (int k = 0; k < MSGD; k++) {
            float w_n = 0.0f; float4 xa_n, xb_n;
            if (k + 1 < MSGD) {
                w_n  = sw[W4T_OFF + (k + 1) * 12 + ty];
                xa_n = *(const float4*)(bufA + (k + 1) * ES + c0);
                xb_n = *(const float4*)(bufA + (k + 1) * ES + 64 + c0);
            }
            float2 ww = make_float2(w0, w0);
            acc[0] = ffma2(ww, make_float2(xa.x, xa.y), acc[0]);
            acc[1] = ffma2(ww, make_float2(xa.z, xa.w), acc[1]);
            acc[2] = ffma2(ww, make_float2(xb.x, xb.y), acc[2]);
            acc[3] = ffma2(ww, make_float2(xb.z, xb.w), acc[3]);
            w0 = w_n; xa = xa_n; xb = xb_n;
        }

        const int* dsts = ids + ES;
#pragma unroll
        for (int p = 0; p < 4; p++) {
            int c = (p < 2) ? (c0 + 2 * p) : (64 + c0 + 2 * (p - 2));
            atomicAdd(&g_agg[dsts[c]     * EF + ty], acc[p].x);
            atomicAdd(&g_agg[dsts[c + 1] * EF + ty], acc[p].y);
        }
    }
}

// ---------------------------------------------------------------------------
// GRU cell + output head, thread-per-node. Also zeroes g_agg for next iter.
// ---------------------------------------------------------------------------
__global__ void gru_kernel(int parity,
                           const float* __restrict__ node_in,
                           const float* __restrict__ wih,  // [30][20]
                           const float* __restrict__ whh,  // [30][10]
                           const float* __restrict__ bih,  // [30]
                           const float* __restrict__ bhh,  // [30]
                           const float* __restrict__ fw,   // [2][10]
                           const float* __restrict__ fb,   // [2]
                           float* __restrict__ out)        // [NN][2] slice
{
    __shared__ float s[600 + 300 + 30 + 30 + 20 + 2];
    int tid = threadIdx.x;
    for (int i = tid; i < 600; i += blockDim.x) s[i] = wih[i];
    for (int i = tid; i < 300; i += blockDim.x) s[600 + i] = whh[i];
    for (int i = tid; i < 30; i += blockDim.x) { s[900 + i] = bih[i]; s[930 + i] = bhh[i]; }
    for (int i = tid; i < 20; i += blockDim.x) s[960 + i] = fw[i];
    for (int i = tid; i < 2; i += blockDim.x) s[980 + i] = fb[i];
    __syncthreads();

    int n = blockIdx.x * blockDim.x + tid;
    if (n >= NN) return;

    const float* __restrict__ hp = g_h[parity] + n * HID;
    float* __restrict__ hn = g_h[1 - parity] + n * HID;

    float x[20], hv[HID];
#pragma unroll
    for (int i = 0; i < EF; i++) { x[i] = g_agg[n * EF + i]; g_agg[n * EF + i] = 0.0f; }
#pragma unroll
    for (int i = 0; i < NIN; i++) x[EF + i] = node_in[n * NIN + i];
#pragma unroll
    for (int i = 0; i < HID; i++) hv[i] = hp[i];

    float gi[30], gh[30];
#pragma unroll
    for (int g = 0; g < 30; g++) {
        float a = s[900 + g];
#pragma unroll
        for (int k = 0; k < 20; k++) a = fmaf(s[g * 20 + k], x[k], a);
        gi[g] = a;
        float b = s[930 + g];
#pragma unroll
        for (int k = 0; k < 10; k++) b = fmaf(s[600 + g * 10 + k], hv[k], b);
        gh[g] = b;
    }

    float hnew[HID];
#pragma unroll
    for (int i = 0; i < HID; i++) {
        float r = 1.0f / (1.0f + expf(-(gi[i] + gh[i])));
        float z = 1.0f / (1.0f + expf(-(gi[10 + i] + gh[10 + i])));
        float nval = tanhf(gi[20 + i] + r * gh[20 + i]);
        float hni = (1.0f - z) * nval + z * hv[i];
        hnew[i] = hni;
        hn[i] = hni;
    }

#pragma unroll
    for (int o = 0; o < 2; o++) {
        float a = s[980 + o];
#pragma unroll
        for (int k = 0; k < HID; k++) a = fmaf(s[960 + o * 10 + k], hnew[k], a);
        out[n * 2 + o] = a;
    }
}

// ---------------------------------------------------------------------------
// Launch
// ---------------------------------------------------------------------------
extern "C" void kernel_launch(void* const* d_in, const int* in_sizes, int n_in,
                              void* d_out, int out_size)
{
    const float* node_in   = (const float*)d_in[0];
    const float* edge_attr = (const float*)d_in[1];
    const float* W1 = (const float*)d_in[2];  const float* b1 = (const float*)d_in[3];
    const float* W2 = (const float*)d_in[4];  const float* b2 = (const float*)d_in[5];
    const float* W3 = (const float*)d_in[6];  const float* b3 = (const float*)d_in[7];
    const float* W4 = (const float*)d_in[8];  const float* b4 = (const float*)d_in[9];
    const float* wih = (const float*)d_in[10]; const float* whh = (const float*)d_in[11];
    const float* bih = (const float*)d_in[12]; const float* bhh = (const float*)d_in[13];
    const float* fw  = (const float*)d_in[14]; const float* fb  = (const float*)d_in[15];
    const int* src = (const int*)d_in[16];
    const int* dst = (const int*)d_in[17];
    float* out = (float*)d_out;

    cudaFuncSetAttribute(edge_kernel,
                         cudaFuncAttributeMaxDynamicSharedMemorySize,
                         EDGE_SMEM_BYTES);

    prep_kernel<<<(WPACK + 255) / 256, 256>>>(W1, b1, W2, b2, W3, b3, W4, b4);
    init_state_kernel<<<(NN * EF + 255) / 256, 256>>>();

    for (int t = 0; t < NITER; t++) {
        int p = t & 1;
        edge_kernel<<<NE / ES, NTHR, EDGE_SMEM_BYTES>>>(p, edge_attr, src, dst);
        gru_kernel<<<(NN + 127) / 128, 128>>>(p, node_in, wih, whh, bih, bhh,
                                              fw, fb, out + (size_t)t * NN * 2);
    }
}

// round 6
// speedup vs baseline: 2.5912x; 1.8892x over previous
#include <cuda_runtime.h>
#include <cuda_bf16.h>
#include <math.h>
#include <stdint.h>

// Problem constants
#define NN     20000
#define NE     320000
#define HID    10
#define NIN    9
#define EF     11
#define NITER  7
#define ES     256      // edges per CTA tile
#define NTHR   256      // 8 warps

// ---------------- smem layout (byte offsets) -------------------------------
// A tile: 256 rows x 200 bf16 (cols 0..191 used: hi 0..95 | lo 96..191)
#define SA        200
#define OFF_A     0
#define A_BYTES   (ES*SA*2)              // 102400
// B regions, [n][k] rows, hi|lo along k, padded strides
#define SB1       72
#define OFF_B1    A_BYTES                // 102400
#define B1_BYTES  (96*SB1*2)             // 13824
#define SB2       200
#define OFF_B2    (OFF_B1 + B1_BYTES)    // 116224
#define B2_BYTES  (96*SB2*2)             // 38400
#define OFF_B3    (OFF_B2 + B2_BYTES)    // 154624
#define OFF_B4    (OFF_B3 + B2_BYTES)    // 193024
#define B4_BYTES  (16*SB2*2)             // 6400
#define OFF_BIAS  (OFF_B4 + B4_BYTES)    // 199424  (304 floats)
#define OFF_IDS   (OFF_BIAS + 304*4)     // 200640  (512 ints)
#define SMEM_REQ  (OFF_IDS + 512*4)      // 202688

// Weight blob (bf16), contiguous B1|B2|B3|B4 with the same in-region layout
#define WB_ELEMS  (96*SB1 + 96*SB2 + 96*SB2 + 16*SB2)   // 48512
__device__ __align__(16) uint16_t g_wb[WB_ELEMS];
__device__ float g_h[2][NN * HID];
__device__ float g_agg[NN * EF];

// ------------------------------ helpers ------------------------------------
__device__ __forceinline__ uint32_t smem_u32(const void* p)
{
    uint32_t a;
    asm("{ .reg .u64 t; cvta.to.shared.u64 t, %1; cvt.u32.u64 %0, t; }"
        : "=r"(a) : "l"(p));
    return a;
}

__device__ __forceinline__ void ldsm_x4(uint32_t& r0, uint32_t& r1,
                                        uint32_t& r2, uint32_t& r3, uint32_t a)
{
    asm volatile("ldmatrix.sync.aligned.m8n8.x4.shared.b16 {%0,%1,%2,%3}, [%4];"
                 : "=r"(r0), "=r"(r1), "=r"(r2), "=r"(r3) : "r"(a));
}

__device__ __forceinline__ void ldsm_x2(uint32_t& r0, uint32_t& r1, uint32_t a)
{
    asm volatile("ldmatrix.sync.aligned.m8n8.x2.shared.b16 {%0,%1}, [%2];"
                 : "=r"(r0), "=r"(r1) : "r"(a));
}

__device__ __forceinline__ void mma_bf16(float& d0, float& d1, float& d2, float& d3,
                                         uint32_t a0, uint32_t a1, uint32_t a2,
                                         uint32_t a3, uint32_t b0, uint32_t b1)
{
    asm volatile(
        "mma.sync.aligned.m16n8k16.row.col.f32.bf16.bf16.f32 "
        "{%0,%1,%2,%3},{%4,%5,%6,%7},{%8,%9},{%0,%1,%2,%3};"
        : "+f"(d0), "+f"(d1), "+f"(d2), "+f"(d3)
        : "r"(a0), "r"(a1), "r"(a2), "r"(a3), "r"(b0), "r"(b1));
}

// hi/lo bf16 split of two floats, packed (low 16 bits = first value)
__device__ __forceinline__ void pack_hilo(float a, float b, uint32_t& hw, uint32_t& lw)
{
    __nv_bfloat162 h2 = __floats2bfloat162_rn(a, b);
    float ra = a - __bfloat162float(h2.x);
    float rb = b - __bfloat162float(h2.y);
    __nv_bfloat162 l2 = __floats2bfloat162_rn(ra, rb);
    hw = *reinterpret_cast<uint32_t*>(&h2);
    lw = *reinterpret_cast<uint32_t*>(&l2);
}

// ---------------------------------------------------------------------------
// Prep: split weights into bf16 hi/lo and pack into the strided blob.
// Region layout (rows = output neuron n, cols = k): hi at col k, lo at K+k.
// ---------------------------------------------------------------------------
__global__ void prep_kernel(const float* __restrict__ W1, const float* __restrict__ W2,
                            const float* __restrict__ W3, const float* __restrict__ W4)
{
    const int E1 = 96 * SB1, E2 = E1 + 96 * SB2, E3 = E2 + 96 * SB2;
    for (int i = blockIdx.x * blockDim.x + threadIdx.x; i < WB_ELEMS;
         i += gridDim.x * blockDim.x) {
        const float* W; int e, stride, K, rows_real, k_real;
        if (i < E1)      { W = W1; e = i;      stride = SB1; K = 32; rows_real = 96; k_real = 31; }
        else if (i < E2) { W = W2; e = i - E1; stride = SB2; K = 96; rows_real = 96; k_real = 96; }
        else if (i < E3) { W = W3; e = i - E2; stride = SB2; K = 96; rows_real = 96; k_real = 96; }
        else             { W = W4; e = i - E3; stride = SB2; K = 96; rows_real = 11; k_real = 96; }
        int row = e / stride, c = e % stride;
        float bits_val = 0.0f;
        uint16_t bits = 0;
        if (row < rows_real && c < 2 * K) {
            int k = (c < K) ? c : c - K;
            if (k < k_real) {
                float w = W[row * k_real + k];
                __nv_bfloat16 hi = __float2bfloat16(w);
                if (c < K) bits = *reinterpret_cast<uint16_t*>(&hi);
                else {
                    __nv_bfloat16 lo = __float2bfloat16(w - __bfloat162float(hi));
                    bits = *reinterpret_cast<uint16_t*>(&lo);
                }
            }
        }
        (void)bits_val;
        g_wb[i] = bits;
    }
}

__global__ void init_state_kernel()
{
    int i = blockIdx.x * blockDim.x + threadIdx.x;
    if (i < NN * HID) g_h[0][i] = 0.0f;
    if (i < NN * EF) g_agg[i] = 0.0f;
}

// ---------------------------------------------------------------------------
// One 96-wide layer: 3 passes (hi*hi, lo*hi, hi*lo), D += A x B^T
// ---------------------------------------------------------------------------
template<int KSTEPS, int SBB>
__device__ __forceinline__ void mma_layer(uint32_t sA, uint32_t sB,
                                          int cA_lo, int cB_lo,
                                          int warp_m, int warp_n,
                                          int a_r, int a_k, int b_n, int b_k,
                                          float (&d)[4][6][4])
{
#pragma unroll 1
    for (int p = 0; p < 3; p++) {
        int cA = (p == 1) ? cA_lo : 0;
        int cB = (p == 2) ? cB_lo : 0;
        uint32_t aBase = sA + (((warp_m * 64 + a_r) * SA + cA + a_k) << 1);
        uint32_t bBase = sB + (((warp_n * 48 + b_n) * SBB + cB + b_k) << 1);
#pragma unroll
        for (int ks = 0; ks < KSTEPS; ks++) {
            uint32_t bb0[6], bb1[6];
#pragma unroll
            for (int j = 0; j < 3; j++) {
                uint32_t t0, t1, t2, t3;
                ldsm_x4(t0, t1, t2, t3, bBase + j * (16 * SBB * 2) + ks * 32);
                bb0[2 * j] = t0; bb1[2 * j] = t1;
                bb0[2 * j + 1] = t2; bb1[2 * j + 1] = t3;
            }
#pragma unroll
            for (int mi = 0; mi < 4; mi++) {
                uint32_t a0, a1, a2, a3;
                ldsm_x4(a0, a1, a2, a3, aBase + mi * (16 * SA * 2) + ks * 32);
#pragma unroll
                for (int ni = 0; ni < 6; ni++)
                    mma_bf16(d[mi][ni][0], d[mi][ni][1], d[mi][ni][2], d[mi][ni][3],
                             a0, a1, a2, a3, bb0[ni], bb1[ni]);
            }
        }
    }
}

// Epilogue: D + bias -> relu -> bf16 hi/lo -> store into A (hi c, lo 96+c)
__device__ __forceinline__ void store_act(char* sm, float (&d)[4][6][4],
                                          const float* bias, int boff,
                                          int warp_m, int warp_n, int lane)
{
    int g = lane >> 2, q = (lane & 3) * 2;
#pragma unroll
    for (int mi = 0; mi < 4; mi++) {
#pragma unroll
        for (int ni = 0; ni < 6; ni++) {
            int r0 = warp_m * 64 + mi * 16 + g;
            int c = warp_n * 48 + ni * 8 + q;
            float bz0 = bias[boff + c], bz1 = bias[boff + c + 1];
            float v0 = fmaxf(d[mi][ni][0] + bz0, 0.0f);
            float v1 = fmaxf(d[mi][ni][1] + bz1, 0.0f);
            float v2 = fmaxf(d[mi][ni][2] + bz0, 0.0f);
            float v3 = fmaxf(d[mi][ni][3] + bz1, 0.0f);
            uint32_t hw, lw;
            pack_hilo(v0, v1, hw, lw);
            *(uint32_t*)(sm + OFF_A + (r0 * SA + c) * 2) = hw;
            *(uint32_t*)(sm + OFF_A + (r0 * SA + 96 + c) * 2) = lw;
            pack_hilo(v2, v3, hw, lw);
            *(uint32_t*)(sm + OFF_A + ((r0 + 8) * SA + c) * 2) = hw;
            *(uint32_t*)(sm + OFF_A + ((r0 + 8) * SA + 96 + c) * 2) = lw;
        }
    }
}

// ---------------------------------------------------------------------------
// Fused edge MLP (mma.sync bf16x3) + scatter-add
// ---------------------------------------------------------------------------
__global__ __launch_bounds__(NTHR, 1)
void edge_kernel(int parity,
                 const float* __restrict__ edge_attr,
                 const int* __restrict__ src, const int* __restrict__ dst,
                 const float* __restrict__ b1, const float* __restrict__ b2,
                 const float* __restrict__ b3, const float* __restrict__ b4)
{
    extern __shared__ char sm[];
    const uint32_t sbase = smem_u32(sm);
    const int tid = threadIdx.x;
    const int wid = tid >> 5, lane = tid & 31;
    const int ebase = blockIdx.x * ES;

    float* bias = (float*)(sm + OFF_BIAS);
    int* ids = (int*)(sm + OFF_IDS);

    // stage weights (97024 B = 6064 float4, L2-resident)
    {
        const float4* gw = (const float4*)g_wb;
        float4* sw = (float4*)(sm + OFF_B1);
        for (int i = tid; i < WB_ELEMS / 8; i += NTHR) sw[i] = gw[i];
    }
    if (tid < 96) { bias[tid] = b1[tid]; bias[96 + tid] = b2[tid]; bias[192 + tid] = b3[tid]; }
    if (tid < 16) bias[288 + tid] = (tid < EF) ? b4[tid] : 0.0f;
    ids[tid] = src[ebase + tid];
    ids[256 + tid] = dst[ebase + tid];
    __syncthreads();

    // gather: thread tid builds A row tid = [x_hi(32) | x_lo(32)]
    {
        float x[32];
        const float* hs = g_h[parity] + (size_t)ids[tid] * HID;
        const float* hd = g_h[parity] + (size_t)ids[256 + tid] * HID;
#pragma unroll
        for (int i = 0; i < HID; i++) { x[i] = hs[i]; x[HID + i] = hd[i]; }
#pragma unroll
        for (int i = 0; i < EF; i++)
            x[2 * HID + i] = edge_attr[(size_t)(ebase + tid) * EF + i];
        x[31] = 0.0f;
#pragma unroll
        for (int p = 0; p < 16; p++) {
            uint32_t hw, lw;
            pack_hilo(x[2 * p], x[2 * p + 1], hw, lw);
            *(uint32_t*)(sm + OFF_A + (tid * SA + 2 * p) * 2) = hw;
            *(uint32_t*)(sm + OFF_A + (tid * SA + 32 + 2 * p) * 2) = lw;
        }
    }
    __syncthreads();

    const int warp_m = wid & 3, warp_n = wid >> 2;
    const int am = lane >> 3;
    const int a_r = ((am & 1) << 3) | (lane & 7);
    const int a_k = (am >> 1) << 3;
    const int b_n = ((am >> 1) << 3) | (lane & 7);
    const int b_k = (am & 1) << 3;

    float d[4][6][4];

    // ---- Layer 1 (K=32 incl pad)
#pragma unroll
    for (int mi = 0; mi < 4; mi++)
#pragma unroll
        for (int ni = 0; ni < 6; ni++)
#pragma unroll
            for (int v = 0; v < 4; v++) d[mi][ni][v] = 0.0f;
    mma_layer<2, SB1>(sbase + OFF_A, sbase + OFF_B1, 32, 32,
                      warp_m, warp_n, a_r, a_k, b_n, b_k, d);
    __syncthreads();
    store_act(sm, d, bias, 0, warp_m, warp_n, lane);
    __syncthreads();

    // ---- Layer 2
#pragma unroll
    for (int mi = 0; mi < 4; mi++)
#pragma unroll
        for (int ni = 0; ni < 6; ni++)
#pragma unroll
            for (int v = 0; v < 4; v++) d[mi][ni][v] = 0.0f;
    mma_layer<6, SB2>(sbase + OFF_A, sbase + OFF_B2, 96, 96,
                      warp_m, warp_n, a_r, a_k, b_n, b_k, d);
    __syncthreads();
    store_act(sm, d, bias, 96, warp_m, warp_n, lane);
    __syncthreads();

    // ---- Layer 3
#pragma unroll
    for (int mi = 0; mi < 4; mi++)
#pragma unroll
        for (int ni = 0; ni < 6; ni++)
#pragma unroll
            for (int v = 0; v < 4; v++) d[mi][ni][v] = 0.0f;
    mma_layer<6, SB2>(sbase + OFF_A, sbase + OFF_B3, 96, 96,
                      warp_m, warp_n, a_r, a_k, b_n, b_k, d);
    __syncthreads();
    store_act(sm, d, bias, 192, warp_m, warp_n, lane);
    __syncthreads();

    // ---- Layer 4: N=16 (11 real); warp covers one n8 tile
    float d4[4][4];
#pragma unroll
    for (int mi = 0; mi < 4; mi++)
#pragma unroll
        for (int v = 0; v < 4; v++) d4[mi][v] = 0.0f;
    {
        const int b4n = (lane & 7);            // row within the warp's n8 tile
        const int b4k = ((lane >> 3) & 1) * 8; // lanes 16-31 repeat (ignored by x2)
#pragma unroll 1
        for (int p = 0; p < 3; p++) {
            int cA = (p == 1) ? 96 : 0;
            int cB = (p == 2) ? 96 : 0;
            uint32_t aBase = sbase + OFF_A + (((warp_m * 64 + a_r) * SA + cA + a_k) << 1);
            uint32_t bBase = sbase + OFF_B4 + (((warp_n * 8 + b4n) * SB2 + cB + b4k) << 1);
#pragma unroll
            for (int ks = 0; ks < 6; ks++) {
                uint32_t bb0, bb1;
                ldsm_x2(bb0, bb1, bBase + ks * 32);
#pragma unroll
                for (int mi = 0; mi < 4; mi++) {
                    uint32_t a0, a1, a2, a3;
                    ldsm_x4(a0, a1, a2, a3, aBase + mi * (16 * SA * 2) + ks * 32);
                    mma_bf16(d4[mi][0], d4[mi][1], d4[mi][2], d4[mi][3],
                             a0, a1, a2, a3, bb0, bb1);
                }
            }
        }
    }

    // scatter-add messages to destinations
    {
        int g = lane >> 2, q = (lane & 3) * 2;
        int c = warp_n * 8 + q;
        float bz0 = (c < EF) ? bias[288 + c] : 0.0f;
        float bz1 = (c + 1 < EF) ? bias[288 + c + 1] : 0.0f;
#pragma unroll
        for (int mi = 0; mi < 4; mi++) {
            int r = warp_m * 64 + mi * 16 + g;
            int dn0 = ids[256 + r];
            int dn1 = ids[256 + r + 8];
            if (c < EF) {
                atomicAdd(&g_agg[(size_t)dn0 * EF + c], d4[mi][0] + bz0);
                atomicAdd(&g_agg[(size_t)dn1 * EF + c], d4[mi][2] + bz0);
            }
            if (c + 1 < EF) {
                atomicAdd(&g_agg[(size_t)dn0 * EF + c + 1], d4[mi][1] + bz1);
                atomicAdd(&g_agg[(size_t)dn1 * EF + c + 1], d4[mi][3] + bz1);
            }
        }
    }
}

// ---------------------------------------------------------------------------
// GRU cell + output head, thread-per-node. Also zeroes g_agg for next iter.
// ---------------------------------------------------------------------------
__global__ void gru_kernel(int parity,
                           const float* __restrict__ node_in,
                           const float* __restrict__ wih,
                           const float* __restrict__ whh,
                           const float* __restrict__ bih,
                           const float* __restrict__ bhh,
                           const float* __restrict__ fw,
                           const float* __restrict__ fb,
                           float* __restrict__ out)
{
    __shared__ float s[600 + 300 + 30 + 30 + 20 + 2];
    int tid = threadIdx.x;
    for (int i = tid; i < 600; i += blockDim.x) s[i] = wih[i];
    for (int i = tid; i < 300; i += blockDim.x) s[600 + i] = whh[i];
    for (int i = tid; i < 30; i += blockDim.x) { s[900 + i] = bih[i]; s[930 + i] = bhh[i]; }
    for (int i = tid; i < 20; i += blockDim.x) s[960 + i] = fw[i];
    for (int i = tid; i < 2; i += blockDim.x) s[980 + i] = fb[i];
    __syncthreads();

    int n = blockIdx.x * blockDim.x + tid;
    if (n >= NN) return;

    const float* __restrict__ hp = g_h[parity] + n * HID;
    float* __restrict__ hn = g_h[1 - parity] + n * HID;

    float x[20], hv[HID];
#pragma unroll
    for (int i = 0; i < EF; i++) { x[i] = g_agg[n * EF + i]; g_agg[n * EF + i] = 0.0f; }
#pragma unroll
    for (int i = 0; i < NIN; i++) x[EF + i] = node_in[n * NIN + i];
#pragma unroll
    for (int i = 0; i < HID; i++) hv[i] = hp[i];

    float gi[30], gh[30];
#pragma unroll
    for (int g = 0; g < 30; g++) {
        float a = s[900 + g];
#pragma unroll
        for (int k = 0; k < 20; k++) a = fmaf(s[g * 20 + k], x[k], a);
        gi[g] = a;
        float b = s[930 + g];
#pragma unroll
        for (int k = 0; k < 10; k++) b = fmaf(s[600 + g * 10 + k], hv[k], b);
        gh[g] = b;
    }

    float hnew[HID];
#pragma unroll
    for (int i = 0; i < HID; i++) {
        float r = 1.0f / (1.0f + expf(-(gi[i] + gh[i])));
        float z = 1.0f / (1.0f + expf(-(gi[10 + i] + gh[10 + i])));
        float nval = tanhf(gi[20 + i] + r * gh[20 + i]);
        float hni = (1.0f - z) * nval + z * hv[i];
        hnew[i] = hni;
        hn[i] = hni;
    }

#pragma unroll
    for (int o = 0; o < 2; o++) {
        float a = s[980 + o];
#pragma unroll
        for (int k = 0; k < HID; k++) a = fmaf(s[960 + o * 10 + k], hnew[k], a);
        out[n * 2 + o] = a;
    }
}

// ---------------------------------------------------------------------------
// Launch
// ---------------------------------------------------------------------------
extern "C" void kernel_launch(void* const* d_in, const int* in_sizes, int n_in,
                              void* d_out, int out_size)
{
    const float* node_in   = (const float*)d_in[0];
    const float* edge_attr = (const float*)d_in[1];
    const float* W1 = (const float*)d_in[2];  const float* b1 = (const float*)d_in[3];
    const float* W2 = (const float*)d_in[4];  const float* b2 = (const float*)d_in[5];
    const float* W3 = (const float*)d_in[6];  const float* b3 = (const float*)d_in[7];
    const float* W4 = (const float*)d_in[8];  const float* b4 = (const float*)d_in[9];
    const float* wih = (const float*)d_in[10]; const float* whh = (const float*)d_in[11];
    const float* bih = (const float*)d_in[12]; const float* bhh = (const float*)d_in[13];
    const float* fw  = (const float*)d_in[14]; const float* fb  = (const float*)d_in[15];
    const int* src = (const int*)d_in[16];
    const int* dst = (const int*)d_in[17];
    float* out = (float*)d_out;

    cudaFuncSetAttribute(edge_kernel,
                         cudaFuncAttributeMaxDynamicSharedMemorySize, SMEM_REQ);

    prep_kernel<<<96, 256>>>(W1, W2, W3, W4);
    init_state_kernel<<<(NN * EF + 255) / 256, 256>>>();

    for (int t = 0; t < NITER; t++) {
        int p = t & 1;
        edge_kernel<<<NE / ES, NTHR, SMEM_REQ>>>(p, edge_attr, src, dst,
                                                 b1, b2, b3, b4);
        gru_kernel<<<(NN + 127) / 128, 128>>>(p, node_in, wih, whh, bih, bhh,
                                              fw, fb, out + (size_t)t * NN * 2);
    }
}

// round 7
// speedup vs baseline: 2.8365x; 1.0947x over previous
#include <cuda_runtime.h>
#include <cuda_bf16.h>
#include <math.h>
#include <stdint.h>

// Problem constants
#define NN     20000
#define NE     320000
#define HID    10
#define NIN    9
#define EF     11
#define NITER  7
#define ES     256      // edges per tile
#define TILES  (NE/ES)  // 1250
#define NTHR   512      // 16 warps
#define NCTA   152      // persistent CTAs (1 per SM on GB300)

// ---------------- smem layout (byte offsets) -------------------------------
#define SA        200
#define OFF_A     0
#define A_BYTES   (ES*SA*2)              // 102400
#define SB1       72
#define OFF_B1    A_BYTES                // 102400
#define B1_BYTES  (96*SB1*2)             // 13824
#define SB2       200
#define OFF_B2    (OFF_B1 + B1_BYTES)    // 116224
#define B2_BYTES  (96*SB2*2)             // 38400
#define OFF_B3    (OFF_B2 + B2_BYTES)    // 154624
#define OFF_B4    (OFF_B3 + B2_BYTES)    // 193024
#define B4_BYTES  (16*SB2*2)             // 6400
#define OFF_BIAS  (OFF_B4 + B4_BYTES)    // 199424  (304 floats)
#define OFF_IDS   (OFF_BIAS + 304*4)     // 200640  (512 ints)
#define SMEM_REQ  (OFF_IDS + 512*4)      // 202688

#define WB_ELEMS  (96*SB1 + 96*SB2 + 96*SB2 + 16*SB2)   // 48512
__device__ __align__(16) uint16_t g_wb[WB_ELEMS];
__device__ float g_h[2][NN * HID];
__device__ float g_agg[NN * EF];
__device__ int   g_tctr[NITER];

// ------------------------------ helpers ------------------------------------
__device__ __forceinline__ uint32_t smem_u32(const void* p)
{
    uint32_t a;
    asm("{ .reg .u64 t; cvta.to.shared.u64 t, %1; cvt.u32.u64 %0, t; }"
        : "=r"(a) : "l"(p));
    return a;
}

__device__ __forceinline__ void ldsm_x4(uint32_t& r0, uint32_t& r1,
                                        uint32_t& r2, uint32_t& r3, uint32_t a)
{
    asm volatile("ldmatrix.sync.aligned.m8n8.x4.shared.b16 {%0,%1,%2,%3}, [%4];"
                 : "=r"(r0), "=r"(r1), "=r"(r2), "=r"(r3) : "r"(a));
}

__device__ __forceinline__ void ldsm_x2(uint32_t& r0, uint32_t& r1, uint32_t a)
{
    asm volatile("ldmatrix.sync.aligned.m8n8.x2.shared.b16 {%0,%1}, [%2];"
                 : "=r"(r0), "=r"(r1) : "r"(a));
}

__device__ __forceinline__ void mma_bf16(float& d0, float& d1, float& d2, float& d3,
                                         uint32_t a0, uint32_t a1, uint32_t a2,
                                         uint32_t a3, uint32_t b0, uint32_t b1)
{
    asm volatile(
        "mma.sync.aligned.m16n8k16.row.col.f32.bf16.bf16.f32 "
        "{%0,%1,%2,%3},{%4,%5,%6,%7},{%8,%9},{%0,%1,%2,%3};"
        : "+f"(d0), "+f"(d1), "+f"(d2), "+f"(d3)
        : "r"(a0), "r"(a1), "r"(a2), "r"(a3), "r"(b0), "r"(b1));
}

__device__ __forceinline__ void pack_hilo(float a, float b, uint32_t& hw, uint32_t& lw)
{
    __nv_bfloat162 h2 = __floats2bfloat162_rn(a, b);
    float ra = a - __bfloat162float(h2.x);
    float rb = b - __bfloat162float(h2.y);
    __nv_bfloat162 l2 = __floats2bfloat162_rn(ra, rb);
    hw = *reinterpret_cast<uint32_t*>(&h2);
    lw = *reinterpret_cast<uint32_t*>(&l2);
}

// ---------------------------------------------------------------------------
// Prep: split weights into bf16 hi/lo, pack into strided blob
// ---------------------------------------------------------------------------
__global__ void prep_kernel(const float* __restrict__ W1, const float* __restrict__ W2,
                            const float* __restrict__ W3, const float* __restrict__ W4)
{
    const int E1 = 96 * SB1, E2 = E1 + 96 * SB2, E3 = E2 + 96 * SB2;
    for (int i = blockIdx.x * blockDim.x + threadIdx.x; i < WB_ELEMS;
         i += gridDim.x * blockDim.x) {
        const float* W; int e, stride, K, rows_real, k_real;
        if (i < E1)      { W = W1; e = i;      stride = SB1; K = 32; rows_real = 96; k_real = 31; }
        else if (i < E2) { W = W2; e = i - E1; stride = SB2; K = 96; rows_real = 96; k_real = 96; }
        else if (i < E3) { W = W3; e = i - E2; stride = SB2; K = 96; rows_real = 96; k_real = 96; }
        else             { W = W4; e = i - E3; stride = SB2; K = 96; rows_real = 11; k_real = 96; }
        int row = e / stride, c = e % stride;
        uint16_t bits = 0;
        if (row < rows_real && c < 2 * K) {
            int k = (c < K) ? c : c - K;
            if (k < k_real) {
                float w = W[row * k_real + k];
                __nv_bfloat16 hi = __float2bfloat16(w);
                if (c < K) bits = *reinterpret_cast<uint16_t*>(&hi);
                else {
                    __nv_bfloat16 lo = __float2bfloat16(w - __bfloat162float(hi));
                    bits = *reinterpret_cast<uint16_t*>(&lo);
                }
            }
        }
        g_wb[i] = bits;
    }
}

__global__ void init_state_kernel()
{
    int i = blockIdx.x * blockDim.x + threadIdx.x;
    if (i < NN * HID) g_h[0][i] = 0.0f;
    if (i < NN * EF) g_agg[i] = 0.0f;
    if (i < NITER) g_tctr[i] = 0;
}

// ---------------------------------------------------------------------------
// One 96-wide layer: 3 passes (hi*hi, lo*hi, hi*lo), D += A x B^T
// Warp tile: 32 rows (MI=2) x 48 cols (NI=6)
// ---------------------------------------------------------------------------
template<int KSTEPS, int SBB>
__device__ __forceinline__ void mma_layer(uint32_t sA, uint32_t sB,
                                          int cA_lo, int cB_lo,
                                          int warp_m, int warp_n,
                                          int a_r, int a_k, int b_n, int b_k,
                                          float (&d)[2][6][4])
{
#pragma unroll 1
    for (int p = 0; p < 3; p++) {
        int cA = (p == 1) ? cA_lo : 0;
        int cB = (p == 2) ? cB_lo : 0;
        uint32_t aBase = sA + (((warp_m * 32 + a_r) * SA + cA + a_k) << 1);
        uint32_t bBase = sB + (((warp_n * 48 + b_n) * SBB + cB + b_k) << 1);
#pragma unroll
        for (int ks = 0; ks < KSTEPS; ks++) {
            uint32_t bb0[6], bb1[6];
#pragma unroll
            for (int j = 0; j < 3; j++) {
                uint32_t t0, t1, t2, t3;
                ldsm_x4(t0, t1, t2, t3, bBase + j * (16 * SBB * 2) + ks * 32);
                bb0[2 * j] = t0; bb1[2 * j] = t1;
                bb0[2 * j + 1] = t2; bb1[2 * j + 1] = t3;
            }
#pragma unroll
            for (int mi = 0; mi < 2; mi++) {
                uint32_t a0, a1, a2, a3;
                ldsm_x4(a0, a1, a2, a3, aBase + mi * (16 * SA * 2) + ks * 32);
#pragma unroll
                for (int ni = 0; ni < 6; ni++)
                    mma_bf16(d[mi][ni][0], d[mi][ni][1], d[mi][ni][2], d[mi][ni][3],
                             a0, a1, a2, a3, bb0[ni], bb1[ni]);
            }
        }
    }
}

__device__ __forceinline__ void store_act(char* sm, float (&d)[2][6][4],
                                          const float* bias, int boff,
                                          int warp_m, int warp_n, int lane)
{
    int g = lane >> 2, q = (lane & 3) * 2;
#pragma unroll
    for (int mi = 0; mi < 2; mi++) {
#pragma unroll
        for (int ni = 0; ni < 6; ni++) {
            int r0 = warp_m * 32 + mi * 16 + g;
            int c = warp_n * 48 + ni * 8 + q;
            float bz0 = bias[boff + c], bz1 = bias[boff + c + 1];
            float v0 = fmaxf(d[mi][ni][0] + bz0, 0.0f);
            float v1 = fmaxf(d[mi][ni][1] + bz1, 0.0f);
            float v2 = fmaxf(d[mi][ni][2] + bz0, 0.0f);
            float v3 = fmaxf(d[mi][ni][3] + bz1, 0.0f);
            uint32_t hw, lw;
            pack_hilo(v0, v1, hw, lw);
            *(uint32_t*)(sm + OFF_A + (r0 * SA + c) * 2) = hw;
            *(uint32_t*)(sm + OFF_A + (r0 * SA + 96 + c) * 2) = lw;
            pack_hilo(v2, v3, hw, lw);
            *(uint32_t*)(sm + OFF_A + ((r0 + 8) * SA + c) * 2) = hw;
            *(uint32_t*)(sm + OFF_A + ((r0 + 8) * SA + 96 + c) * 2) = lw;
        }
    }
}

// ---------------------------------------------------------------------------
// Persistent fused edge MLP (mma.sync bf16x3) + scatter-add
// ---------------------------------------------------------------------------
__global__ __launch_bounds__(NTHR, 1)
void edge_kernel(int iter, int parity,
                 const float* __restrict__ edge_attr,
                 const int* __restrict__ src, const int* __restrict__ dst,
                 const float* __restrict__ b1, const float* __restrict__ b2,
                 const float* __restrict__ b3, const float* __restrict__ b4)
{
    extern __shared__ char sm[];
    const uint32_t sbase = smem_u32(sm);
    const int tid = threadIdx.x;
    const int wid = tid >> 5, lane = tid & 31;

    float* bias = (float*)(sm + OFF_BIAS);
    int* ids = (int*)(sm + OFF_IDS);
    __shared__ int s_tile;

    // stage weights + biases ONCE per CTA
    {
        const float4* gw = (const float4*)g_wb;
        float4* sw = (float4*)(sm + OFF_B1);
        for (int i = tid; i < WB_ELEMS / 8; i += NTHR) sw[i] = gw[i];
    }
    if (tid < 96) { bias[tid] = b1[tid]; bias[96 + tid] = b2[tid]; bias[192 + tid] = b3[tid]; }
    if (tid >= 96 && tid < 112) bias[288 + tid - 96] = (tid - 96 < EF) ? b4[tid - 96] : 0.0f;

    const int warp_m = wid & 7, warp_n = wid >> 3;
    const int am = lane >> 3;
    const int a_r = ((am & 1) << 3) | (lane & 7);
    const int a_k = (am >> 1) << 3;
    const int b_n = ((am >> 1) << 3) | (lane & 7);
    const int b_k = (am & 1) << 3;

    while (true) {
        if (tid == 0) s_tile = atomicAdd(&g_tctr[iter], 1);
        __syncthreads();                 // also: all done with previous tile
        const int tile = s_tile;
        if (tile >= TILES) break;
        const int ebase = tile * ES;

        // edge ids
        ids[tid] = (tid < 256) ? src[ebase + tid] : dst[ebase + tid - 256];
        __syncthreads();

        // gather: 2 threads per row; half 0 = cols 0..15, half 1 = cols 16..31
        {
            int row = tid >> 1, half = tid & 1;
            float x[16];
            if (half == 0) {
                const float* hs = g_h[parity] + (size_t)ids[row] * HID;
                const float* hd = g_h[parity] + (size_t)ids[256 + row] * HID;
#pragma unroll
                for (int i = 0; i < HID; i++) x[i] = hs[i];
#pragma unroll
                for (int i = 0; i < 6; i++) x[HID + i] = hd[i];
            } else {
                const float* hd = g_h[parity] + (size_t)ids[256 + row] * HID;
#pragma unroll
                for (int i = 0; i < 4; i++) x[i] = hd[6 + i];
#pragma unroll
                for (int i = 0; i < EF; i++)
                    x[4 + i] = edge_attr[(size_t)(ebase + row) * EF + i];
                x[15] = 0.0f;
            }
            int cb = half * 16;
#pragma unroll
            for (int p = 0; p < 8; p++) {
                uint32_t hw, lw;
                pack_hilo(x[2 * p], x[2 * p + 1], hw, lw);
                *(uint32_t*)(sm + OFF_A + (row * SA + cb + 2 * p) * 2) = hw;
                *(uint32_t*)(sm + OFF_A + (row * SA + 32 + cb + 2 * p) * 2) = lw;
            }
        }
        __syncthreads();

        float d[2][6][4];

        // ---- Layer 1 (K=32 incl pad)
#pragma unroll
        for (int mi = 0; mi < 2; mi++)
#pragma unroll
            for (int ni = 0; ni < 6; ni++)
#pragma unroll
                for (int v = 0; v < 4; v++) d[mi][ni][v] = 0.0f;
        mma_layer<2, SB1>(sbase + OFF_A, sbase + OFF_B1, 32, 32,
                          warp_m, warp_n, a_r, a_k, b_n, b_k, d);
        __syncthreads();
        store_act(sm, d, bias, 0, warp_m, warp_n, lane);
        __syncthreads();

        // ---- Layer 2
#pragma unroll
        for (int mi = 0; mi < 2; mi++)
#pragma unroll
            for (int ni = 0; ni < 6; ni++)
#pragma unroll
                for (int v = 0; v < 4; v++) d[mi][ni][v] = 0.0f;
        mma_layer<6, SB2>(sbase + OFF_A, sbase + OFF_B2, 96, 96,
                          warp_m, warp_n, a_r, a_k, b_n, b_k, d);
        __syncthreads();
        store_act(sm, d, bias, 96, warp_m, warp_n, lane);
        __syncthreads();

        // ---- Layer 3
#pragma unroll
        for (int mi = 0; mi < 2; mi++)
#pragma unroll
            for (int ni = 0; ni < 6; ni++)
#pragma unroll
                for (int v = 0; v < 4; v++) d[mi][ni][v] = 0.0f;
        mma_layer<6, SB2>(sbase + OFF_A, sbase + OFF_B3, 96, 96,
                          warp_m, warp_n, a_r, a_k, b_n, b_k, d);
        __syncthreads();
        store_act(sm, d, bias, 192, warp_m, warp_n, lane);
        __syncthreads();

        // ---- Layer 4: N=16 (11 real); warp_n selects n8 tile 0/1
        float d4[2][4];
#pragma unroll
        for (int mi = 0; mi < 2; mi++)
#pragma unroll
            for (int v = 0; v < 4; v++) d4[mi][v] = 0.0f;
        {
            const int b4n = (lane & 7);
            const int b4k = ((lane >> 3) & 1) * 8;
#pragma unroll 1
            for (int p = 0; p < 3; p++) {
                int cA = (p == 1) ? 96 : 0;
                int cB = (p == 2) ? 96 : 0;
                uint32_t aBase = sbase + OFF_A + (((warp_m * 32 + a_r) * SA + cA + a_k) << 1);
                uint32_t bBase = sbase + OFF_B4 + (((warp_n * 8 + b4n) * SB2 + cB + b4k) << 1);
#pragma unroll
                for (int ks = 0; ks < 6; ks++) {
                    uint32_t bb0, bb1;
                    ldsm_x2(bb0, bb1, bBase + ks * 32);
#pragma unroll
                    for (int mi = 0; mi < 2; mi++) {
                        uint32_t a0, a1, a2, a3;
                        ldsm_x4(a0, a1, a2, a3, aBase + mi * (16 * SA * 2) + ks * 32);
                        mma_bf16(d4[mi][0], d4[mi][1], d4[mi][2], d4[mi][3],
                                 a0, a1, a2, a3, bb0, bb1);
                    }
                }
            }
        }

        // scatter-add messages to destinations
        {
            int g = lane >> 2, q = (lane & 3) * 2;
            int c = warp_n * 8 + q;
            float bz0 = (c < EF) ? bias[288 + c] : 0.0f;
            float bz1 = (c + 1 < EF) ? bias[288 + c + 1] : 0.0f;
#pragma unroll
            for (int mi = 0; mi < 2; mi++) {
                int r = warp_m * 32 + mi * 16 + g;
                int dn0 = ids[256 + r];
                int dn1 = ids[256 + r + 8];
                if (c < EF) {
                    atomicAdd(&g_agg[(size_t)dn0 * EF + c], d4[mi][0] + bz0);
                    atomicAdd(&g_agg[(size_t)dn1 * EF + c], d4[mi][2] + bz0);
                }
                if (c + 1 < EF) {
                    atomicAdd(&g_agg[(size_t)dn0 * EF + c + 1], d4[mi][1] + bz1);
                    atomicAdd(&g_agg[(size_t)dn1 * EF + c + 1], d4[mi][3] + bz1);
                }
            }
        }
    }
}

// ---------------------------------------------------------------------------
// GRU cell + output head, thread-per-node. Also zeroes g_agg for next iter.
// ---------------------------------------------------------------------------
__global__ void gru_kernel(int parity,
                           const float* __restrict__ node_in,
                           const float* __restrict__ wih,
                           const float* __restrict__ whh,
                           const float* __restrict__ bih,
                           const float* __restrict__ bhh,
                           const float* __restrict__ fw,
                           const float* __restrict__ fb,
                           float* __restrict__ out)
{
    __shared__ float s[600 + 300 + 30 + 30 + 20 + 2];
    int tid = threadIdx.x;
    for (int i = tid; i < 600; i += blockDim.x) s[i] = wih[i];
    for (int i = tid; i < 300; i += blockDim.x) s[600 + i] = whh[i];
    for (int i = tid; i < 30; i += blockDim.x) { s[900 + i] = bih[i]; s[930 + i] = bhh[i]; }
    for (int i = tid; i < 20; i += blockDim.x) s[960 + i] = fw[i];
    for (int i = tid; i < 2; i += blockDim.x) s[980 + i] = fb[i];
    __syncthreads();

    int n = blockIdx.x * blockDim.x + tid;
    if (n >= NN) return;

    const float* __restrict__ hp = g_h[parity] + n * HID;
    float* __restrict__ hn = g_h[1 - parity] + n * HID;

    float x[20], hv[HID];
#pragma unroll
    for (int i = 0; i < EF; i++) { x[i] = g_agg[n * EF + i]; g_agg[n * EF + i] = 0.0f; }
#pragma unroll
    for (int i = 0; i < NIN; i++) x[EF + i] = node_in[n * NIN + i];
#pragma unroll
    for (int i = 0; i < HID; i++) hv[i] = hp[i];

    float gi[30], gh[30];
#pragma unroll
    for (int g = 0; g < 30; g++) {
        float a = s[900 + g];
#pragma unroll
        for (int k = 0; k < 20; k++) a = fmaf(s[g * 20 + k], x[k], a);
        gi[g] = a;
        float b = s[930 + g];
#pragma unroll
        for (int k = 0; k < 10; k++) b = fmaf(s[600 + g * 10 + k], hv[k], b);
        gh[g] = b;
    }

    float hnew[HID];
#pragma unroll
    for (int i = 0; i < HID; i++) {
        float r = 1.0f / (1.0f + expf(-(gi[i] + gh[i])));
        float z = 1.0f / (1.0f + expf(-(gi[10 + i] + gh[10 + i])));
        float nval = tanhf(gi[20 + i] + r * gh[20 + i]);
        float hni = (1.0f - z) * nval + z * hv[i];
        hnew[i] = hni;
        hn[i] = hni;
    }

#pragma unroll
    for (int o = 0; o < 2; o++) {
        float a = s[980 + o];
#pragma unroll
        for (int k = 0; k < HID; k++) a = fmaf(s[960 + o * 10 + k], hnew[k], a);
        out[n * 2 + o] = a;
    }
}

// ---------------------------------------------------------------------------
// Launch
// ---------------------------------------------------------------------------
extern "C" void kernel_launch(void* const* d_in, const int* in_sizes, int n_in,
                              void* d_out, int out_size)
{
    const float* node_in   = (const float*)d_in[0];
    const float* edge_attr = (const float*)d_in[1];
    const float* W1 = (const float*)d_in[2];  const float* b1 = (const float*)d_in[3];
    const float* W2 = (const float*)d_in[4];  const float* b2 = (const float*)d_in[5];
    const float* W3 = (const float*)d_in[6];  const float* b3 = (const float*)d_in[7];
    const float* W4 = (const float*)d_in[8];  const float* b4 = (const float*)d_in[9];
    const float* wih = (const float*)d_in[10]; const float* whh = (const float*)d_in[11];
    const float* bih = (const float*)d_in[12]; const float* bhh = (const float*)d_in[13];
    const float* fw  = (const float*)d_in[14]; const float* fb  = (const float*)d_in[15];
    const int* src = (const int*)d_in[16];
    const int* dst = (const int*)d_in[17];
    float* out = (float*)d_out;

    cudaFuncSetAttribute(edge_kernel,
                         cudaFuncAttributeMaxDynamicSharedMemorySize, SMEM_REQ);

    prep_kernel<<<96, 256>>>(W1, W2, W3, W4);
    init_state_kernel<<<(NN * EF + 255) / 256, 256>>>();

    for (int t = 0; t < NITER; t++) {
        int p = t & 1;
        edge_kernel<<<NCTA, NTHR, SMEM_REQ>>>(t, p, edge_attr, src, dst,
                                              b1, b2, b3, b4);
        gru_kernel<<<(NN + 127) / 128, 128>>>(p, node_in, wih, whh, bih, bhh,
                                              fw, fb, out + (size_t)t * NN * 2);
    }
}